// round 16
// baseline (speedup 1.0000x reference)
#include <cuda_runtime.h>
#include <cuda_bf16.h>
#include <math.h>
#include <stdint.h>

#define NN 50000
#define NE 800000
#define C 128

// Scratch (device globals; no allocation allowed)
// g_M1/2/3 hold the folded matrices TRANSPOSED: g_M[j*C + i] = M[i][j]
__device__ float g_M1[C * C];
__device__ float g_M2[C * C];
__device__ float g_M3[C * C];
__device__ float g_cb[C];
__device__ float g_A[NN * C];
__device__ float g_B[NN * C];

__device__ __forceinline__ uint32_t smem_u32(const void* p) {
    uint32_t a;
    asm("{ .reg .u64 t; cvta.to.shared.u64 t, %1; cvt.u32.u64 %0, t; }"
        : "=r"(a) : "l"(p));
    return a;
}
__device__ __forceinline__ void ldsm_x4(uint32_t* r, uint32_t addr) {
    asm volatile("ldmatrix.sync.aligned.m8n8.x4.shared.b16 {%0,%1,%2,%3}, [%4];"
                 : "=r"(r[0]), "=r"(r[1]), "=r"(r[2]), "=r"(r[3]) : "r"(addr));
}
__device__ __forceinline__ void mma_bf16(float* c, const uint32_t* a,
                                         uint32_t b0, uint32_t b1) {
    asm volatile(
        "mma.sync.aligned.m16n8k16.row.col.f32.bf16.bf16.f32 "
        "{%0,%1,%2,%3}, {%4,%5,%6,%7}, {%8,%9}, {%0,%1,%2,%3};"
        : "+f"(c[0]), "+f"(c[1]), "+f"(c[2]), "+f"(c[3])
        : "r"(a[0]), "r"(a[1]), "r"(a[2]), "r"(a[3]), "r"(b0), "r"(b1));
}
__device__ __forceinline__ void mma3_pair(float* c0, float* c1,
                                          const uint32_t* ah, const uint32_t* al,
                                          const uint32_t* bh, const uint32_t* bl) {
    mma_bf16(c0, ah, bh[0], bh[1]);
    mma_bf16(c0, al, bh[0], bh[1]);
    mma_bf16(c0, ah, bl[0], bl[1]);
    mma_bf16(c1, ah, bh[2], bh[3]);
    mma_bf16(c1, al, bh[2], bh[3]);
    mma_bf16(c1, ah, bl[2], bl[3]);
}
__device__ __forceinline__ void splitf2(float2 v, uint32_t& h, uint32_t& l) {
    __nv_bfloat162 hh = __floats2bfloat162_rn(v.x, v.y);
    __nv_bfloat162 ll = __floats2bfloat162_rn(v.x - __bfloat162float(hh.x),
                                              v.y - __bfloat162float(hh.y));
    h = *(uint32_t*)&hh;
    l = *(uint32_t*)&ll;
}

#define PITCH 272
// XOR swizzle for 256B-pitch tiles: 16B-chunk index ^= (row & 7)
#define SWZ(o) ((o) ^ ((((o) >> 8) & 7) << 4))

// ---------------------------------------------------------------------------
// K1: fold the three input linears through enc_W. Stores TRANSPOSED.
// grid (32, 3) = 96 blocks (R15, confirmed win).
// ---------------------------------------------------------------------------
__global__ void fold_kernel(const float* __restrict__ node_W,
                            const float* __restrict__ nbr_W,
                            const float* __restrict__ gud_W,
                            const float* __restrict__ enc_W) {
    int m = blockIdx.y;
    const float* W = (m == 0) ? node_W : ((m == 1) ? nbr_W : gud_W);
    const float* E = enc_W + m * C * C;
    float* M = (m == 0) ? g_M1 : ((m == 1) ? g_M2 : g_M3);

    int j = threadIdx.x & 127;
    int iq = threadIdx.x >> 7;   // 0..1
    int i0 = blockIdx.x * 4;
    for (int i = i0 + iq; i < i0 + 4; i += 2) {
        float s = 0.f;
#pragma unroll 8
        for (int h = 0; h < C; h++) s += W[i * C + h] * E[h * C + j];
        M[j * C + i] = s;   // transposed store
    }
}

// cb: 512 threads, 4-way split over the 384 h-terms, smem reduction (R15).
__global__ void cb_kernel(const float* __restrict__ node_b,
                          const float* __restrict__ nbr_b,
                          const float* __restrict__ gud_b,
                          const float* __restrict__ enc_W,
                          const float* __restrict__ enc_b) {
    __shared__ float part[4][C];
    int j = threadIdx.x & 127;
    int q = threadIdx.x >> 7;   // 0..3
    float s = 0.f;
    for (int h = q * 96; h < (q + 1) * 96; h++) {
        float b = (h < 128) ? node_b[h] : ((h < 256) ? nbr_b[h - 128] : gud_b[h - 256]);
        s += b * enc_W[h * C + j];
    }
    part[q][j] = s;
    __syncthreads();
    if (q == 0)
        g_cb[j] = enc_b[j] + part[0][j] + part[1][j] + part[2][j] + part[3][j];
}

// ---------------------------------------------------------------------------
// K2: single-pass node precompute, 512 threads / 16 warps (R13/R15, frozen).
// ---------------------------------------------------------------------------
#define NSMEM  208896
#define NODE_GRID 148

__global__ __launch_bounds__(512, 1)
void node_mma_direct(const float* __restrict__ x, const float* __restrict__ g) {
    extern __shared__ float smf[];
    char* smc = (char*)smf;
    uint32_t su = smem_u32(smf);
    int tid = threadIdx.x;
    int tx = tid & 31, wid = tid >> 5;
    int sub = wid & 7, nh = wid >> 3;
    int gwid = blockIdx.x * 8 + sub;

#pragma unroll
    for (int mi = 0; mi < 3; mi++) {
        const float* Wm = (mi == 0) ? g_M1 : ((mi == 1) ? g_M2 : g_M3);
        char* base = smc + mi * 69632;
        for (int idx = tid; idx < C * C; idx += 512) {
            int n = idx >> 7, k = idx & 127;
            float w = Wm[idx];
            __nv_bfloat16 h = __float2bfloat16(w);
            __nv_bfloat16 l = __float2bfloat16(w - __bfloat162float(h));
            *(__nv_bfloat16*)(base + n * PITCH + k * 2) = h;
            *(__nv_bfloat16*)(base + 34816 + n * PITCH + k * 2) = l;
        }
    }
    __syncthreads();

    int gr = tx >> 2;
    int gc2 = (tx & 3) * 2;
    uint32_t b_row = (tx & 7) + 8 * (tx >> 4);
    uint32_t b_k16 = ((tx >> 3) & 1) * 16;
    uint32_t nbase = (uint32_t)(nh * 64);

    const int NTW = NN / 16;
    const int WSTRIDE = NODE_GRID * 8;

    for (int t = gwid; t < NTW; t += WSTRIDE) {
        int row0 = t * 16;
        const float* xr0 = x + (size_t)(row0 + gr) * C + gc2;
        const float* xr8 = xr0 + 8 * C;
        const float* gr0 = g + (size_t)(row0 + gr) * C + gc2;
        const float* gr8 = gr0 + 8 * C;

        float accA[8][4], accB[8][4];
#pragma unroll
        for (int a = 0; a < 8; a++)
#pragma unroll
            for (int b = 0; b < 4; b++) { accA[a][b] = 0.f; accB[a][b] = 0.f; }

        float2 xv[4];
        xv[0] = *(const float2*)(xr0);
        xv[1] = *(const float2*)(xr8);
        xv[2] = *(const float2*)(xr0 + 8);
        xv[3] = *(const float2*)(xr8 + 8);

#pragma unroll
        for (int ks = 0; ks < 8; ks++) {
            int kb = ks * 16;
            float2 gv[4];
            gv[0] = *(const float2*)(gr0 + kb);
            gv[1] = *(const float2*)(gr8 + kb);
            gv[2] = *(const float2*)(gr0 + kb + 8);
            gv[3] = *(const float2*)(gr8 + kb + 8);

            uint32_t ah[4], al[4];
            splitf2(xv[0], ah[0], al[0]);
            splitf2(xv[1], ah[1], al[1]);
            splitf2(xv[2], ah[2], al[2]);
            splitf2(xv[3], ah[3], al[3]);
            uint32_t bcol = ks * 32 + b_k16;
#pragma unroll
            for (int np = 0; np < 4; np++) {
                uint32_t bro = (nbase + np * 16 + b_row) * PITCH + bcol;
                uint32_t bh[4], bl[4];
                ldsm_x4(bh, su + bro);
                ldsm_x4(bl, su + 34816 + bro);
                mma3_pair(accA[2 * np], accA[2 * np + 1], ah, al, bh, bl);
                ldsm_x4(bh, su + 69632 + bro);
                ldsm_x4(bl, su + 69632 + 34816 + bro);
                mma3_pair(accB[2 * np], accB[2 * np + 1], ah, al, bh, bl);
            }

            if (ks < 7) {
                int kb2 = kb + 16;
                xv[0] = *(const float2*)(xr0 + kb2);
                xv[1] = *(const float2*)(xr8 + kb2);
                xv[2] = *(const float2*)(xr0 + kb2 + 8);
                xv[3] = *(const float2*)(xr8 + kb2 + 8);
            }

            uint32_t gh[4], gl[4];
            splitf2(gv[0], gh[0], gl[0]);
            splitf2(gv[1], gh[1], gl[1]);
            splitf2(gv[2], gh[2], gl[2]);
            splitf2(gv[3], gh[3], gl[3]);
#pragma unroll
            for (int np = 0; np < 4; np++) {
                uint32_t bro = (nbase + np * 16 + b_row) * PITCH + bcol;
                uint32_t bh[4], bl[4];
                ldsm_x4(bh, su + 139264 + bro);
                ldsm_x4(bl, su + 139264 + 34816 + bro);
                mma3_pair(accB[2 * np], accB[2 * np + 1], gh, gl, bh, bl);
            }
        }

        float* pa = g_A + (size_t)(row0 + gr) * C + nbase + gc2;
        float* pb = g_B + (size_t)(row0 + gr) * C + nbase + gc2;
#pragma unroll
        for (int nf = 0; nf < 8; nf++) {
            int col = nf * 8;
            *(float2*)(pa + col) = make_float2(accA[nf][0], accA[nf][1]);
            *(float2*)(pa + 8 * C + col) = make_float2(accA[nf][2], accA[nf][3]);
            *(float2*)(pb + col) = make_float2(accB[nf][0], accB[nf][1]);
            *(float2*)(pb + 8 * C + col) = make_float2(accB[nf][2], accB[nf][3]);
        }
    }
}

// ---------------------------------------------------------------------------
// K3: split-bf16 edge kernel — R13 warp-private structure + INTRA-WARP
// SOFTWARE PIPELINING: A strips double-buffered; gather of tile t+1 is
// interleaved into the MMA k-loop of tile t (2 rows per ks). No inter-warp
// coupling. XOR-swizzled 256B-pitch smem for both A and B.
// SMEM (bytes):
//   [0..1536)          params: vb1[64] vw2[64] pb1[128] pw2[128]
//   [2048..133120)     A: 8 warps x 2 bufs x (hi 16x256 + lo 16x256) = 16384/warp
//   [133120..182272)   B hi: 192 x 256 (swizzled)
//   [182272..231424)   B lo
// ---------------------------------------------------------------------------
#define A_OFF    2048
#define A_WARPX  16384
#define EB_H     133120
#define EB_L     182272
#define SMEM_E   231424
#define NGRID    148

__global__ __launch_bounds__(256, 1)
void edge_kernel_mma(const int* __restrict__ ei,
                     const float* __restrict__ vp_W1, const float* __restrict__ vp_b1,
                     const float* __restrict__ vp_W2, const float* __restrict__ vp_b2,
                     const float* __restrict__ pol_W1, const float* __restrict__ pol_b1,
                     const float* __restrict__ pol_W2, const float* __restrict__ pol_b2,
                     float* __restrict__ out) {
    extern __shared__ float smf[];
    char* smc = (char*)smf;
    uint32_t su = smem_u32(smf);
    int tid = threadIdx.x;
    int tx = tid & 31, wid = tid >> 5;

    // --- stage split weights B[n][k] (swizzled 256 pitch) ---
    for (int idx = tid; idx < 192 * C; idx += 256) {
        int n = idx >> 7, k = idx & 127;
        float w = (n < 64) ? vp_W1[k * 64 + n] : pol_W1[k * C + (n - 64)];
        __nv_bfloat16 wh = __float2bfloat16(w);
        __nv_bfloat16 wl = __float2bfloat16(w - __bfloat162float(wh));
        uint32_t off = SWZ((uint32_t)(n * 256 + k * 2));
        *(__nv_bfloat16*)(smc + EB_H + off) = wh;
        *(__nv_bfloat16*)(smc + EB_L + off) = wl;
    }
    if (tid < 64) { smf[tid] = vp_b1[tid]; smf[64 + tid] = vp_W2[tid]; }
    if (tid < 128) { smf[128 + tid] = pol_b1[tid]; smf[256 + tid] = pol_W2[tid]; }
    __syncthreads();

    float vb2v = vp_b2[0], pb2v = pol_b2[0];
    float4 cb4 = ((const float4*)g_cb)[tx];
    if (blockIdx.x == 0 && tid == 0) out[3L * NE] = 0.f;  // value_loss

    uint32_t aw = (uint32_t)(A_OFF + wid * A_WARPX);   // byte offset in smc
    uint32_t a_row = (tx & 7) + 8 * ((tx >> 3) & 1);
    uint32_t a_k16 = (tx >> 4) * 16;
    uint32_t b_row = (tx & 7) + 8 * (tx >> 4);
    uint32_t b_k16 = ((tx >> 3) & 1) * 16;

    const int ntiles = NE / 128;  // 6250

    // gather one edge row into buffer (swizzled)
#define GATHER_ROW(ebase, mrow, bufo)                                          \
    do {                                                                       \
        int rr = ei[(ebase) + (mrow)];                                         \
        int cc = ei[NE + (ebase) + (mrow)];                                    \
        float4 a = ((const float4*)(g_A + (size_t)rr * C))[tx];                \
        float4 b = ((const float4*)(g_B + (size_t)cc * C))[tx];                \
        float z0 = fmaxf(a.x + b.x + cb4.x, 0.f);                              \
        float z1 = fmaxf(a.y + b.y + cb4.y, 0.f);                              \
        float z2 = fmaxf(a.z + b.z + cb4.z, 0.f);                              \
        float z3 = fmaxf(a.w + b.w + cb4.w, 0.f);                              \
        __nv_bfloat162 h01 = __floats2bfloat162_rn(z0, z1);                    \
        __nv_bfloat162 h23 = __floats2bfloat162_rn(z2, z3);                    \
        __nv_bfloat162 l01 = __floats2bfloat162_rn(                            \
            z0 - __bfloat162float(h01.x), z1 - __bfloat162float(h01.y));       \
        __nv_bfloat162 l23 = __floats2bfloat162_rn(                            \
            z2 - __bfloat162float(h23.x), z3 - __bfloat162float(h23.y));       \
        uint2 hv, lv;                                                          \
        hv.x = *(uint32_t*)&h01; hv.y = *(uint32_t*)&h23;                      \
        lv.x = *(uint32_t*)&l01; lv.y = *(uint32_t*)&l23;                      \
        uint32_t soff = SWZ((uint32_t)((mrow) * 256 + tx * 8));                \
        *(uint2*)(smc + aw + (bufo) + soff) = hv;                              \
        *(uint2*)(smc + aw + (bufo) + 4096 + soff) = lv;                       \
    } while (0)

    // prologue: gather first tile into buf0
    {
        long ebase = (long)blockIdx.x * 128 + wid * 16;
#pragma unroll 4
        for (int m = 0; m < 16; m++) GATHER_ROW(ebase, m, 0);
    }
    __syncwarp();

    int buf = 0;
    for (int t = blockIdx.x; t < ntiles; t += NGRID) {
        long base = (long)t * 128 + wid * 16;
        int tn = t + NGRID;
        bool pre = (tn < ntiles);
        long nbase2 = (long)tn * 128 + wid * 16;
        uint32_t bufo = (uint32_t)(buf * 8192);
        uint32_t nbufo = (uint32_t)((buf ^ 1) * 8192);

        float acc[24][4];
#pragma unroll
        for (int a = 0; a < 24; a++)
#pragma unroll
            for (int b = 0; b < 4; b++) acc[a][b] = 0.f;

#pragma unroll
        for (int ks = 0; ks < 8; ks++) {
            uint32_t acol = ks * 32 + a_k16;
            uint32_t lin = a_row * 256 + acol;
            uint32_t ah[4], al[4];
            ldsm_x4(ah, su + aw + bufo + SWZ(lin));
            ldsm_x4(al, su + aw + bufo + 4096 + SWZ(lin));
            uint32_t bcol = ks * 32 + b_k16;
#pragma unroll
            for (int np = 0; np < 12; np++) {
                uint32_t blin = (np * 16 + b_row) * 256 + bcol;
                uint32_t bsw = SWZ(blin);
                uint32_t bh[4], bl[4];
                ldsm_x4(bh, su + EB_H + bsw);
                ldsm_x4(bl, su + EB_L + bsw);
                mma3_pair(acc[2 * np], acc[2 * np + 1], ah, al, bh, bl);
            }
            // interleaved gather: 2 rows of NEXT tile into other buffer
            if (pre) {
                GATHER_ROW(nbase2, 2 * ks, nbufo);
                GATHER_ROW(nbase2, 2 * ks + 1, nbufo);
            }
        }
        __syncwarp();   // next-tile STS visible to all lanes before its ldsm

        // ---- epilogue: heads + quad reduce ----
        float vr = 0.f, vr8 = 0.f, lr = 0.f, lr8 = 0.f;
#pragma unroll
        for (int nt = 0; nt < 24; nt++) {
            int c0 = nt * 8 + 2 * (tx & 3);
            if (nt < 8) {
                float b0 = smf[c0], w0 = smf[64 + c0];
                float b1 = smf[c0 + 1], w1 = smf[64 + c0 + 1];
                vr  += fmaxf(acc[nt][0] + b0, 0.f) * w0 + fmaxf(acc[nt][1] + b1, 0.f) * w1;
                vr8 += fmaxf(acc[nt][2] + b0, 0.f) * w0 + fmaxf(acc[nt][3] + b1, 0.f) * w1;
            } else {
                int ix = c0 - 64;
                float b0 = smf[128 + ix], w0 = smf[256 + ix];
                float b1 = smf[128 + ix + 1], w1 = smf[256 + ix + 1];
                lr  += fmaxf(acc[nt][0] + b0, 0.f) * w0 + fmaxf(acc[nt][1] + b1, 0.f) * w1;
                lr8 += fmaxf(acc[nt][2] + b0, 0.f) * w0 + fmaxf(acc[nt][3] + b1, 0.f) * w1;
            }
        }
#pragma unroll
        for (int off = 1; off <= 2; off <<= 1) {
            vr  += __shfl_xor_sync(0xffffffffu, vr, off);
            vr8 += __shfl_xor_sync(0xffffffffu, vr8, off);
            lr  += __shfl_xor_sync(0xffffffffu, lr, off);
            lr8 += __shfl_xor_sync(0xffffffffu, lr8, off);
        }
        if ((tx & 3) == 0) {
            int r = tx >> 2;
            long e0 = base + r;
            long e1 = base + r + 8;
            float v0 = vr + vb2v, v1 = vr8 + vb2v;
            float p0 = 1.f / (1.f + expf(-(lr + pb2v)));
            float p1 = 1.f / (1.f + expf(-(lr8 + pb2v)));
            out[e0] = v0;
            out[e1] = v1;
            out[NE + e0] = p0;
            out[NE + e1] = p1;
            out[2L * NE + e0] = (p0 > 0.5f) ? 1.f : 0.f;
            out[2L * NE + e1] = (p1 > 0.5f) ? 1.f : 0.f;
        }
        buf ^= 1;
    }
#undef GATHER_ROW
}

// ---------------------------------------------------------------------------
extern "C" void kernel_launch(void* const* d_in, const int* in_sizes, int n_in,
                              void* d_out, int out_size) {
    const float* x       = (const float*)d_in[0];
    const int*   ei      = (const int*)d_in[1];
    const float* gf      = (const float*)d_in[2];
    const float* node_W  = (const float*)d_in[3];
    const float* node_b  = (const float*)d_in[4];
    const float* nbr_W   = (const float*)d_in[5];
    const float* nbr_b   = (const float*)d_in[6];
    const float* gud_W   = (const float*)d_in[7];
    const float* gud_b   = (const float*)d_in[8];
    const float* enc_W   = (const float*)d_in[9];
    const float* enc_b   = (const float*)d_in[10];
    const float* vp_W1   = (const float*)d_in[11];
    const float* vp_b1   = (const float*)d_in[12];
    const float* vp_W2   = (const float*)d_in[13];
    const float* vp_b2   = (const float*)d_in[14];
    const float* pol_W1  = (const float*)d_in[15];
    const float* pol_b1  = (const float*)d_in[16];
    const float* pol_W2  = (const float*)d_in[17];
    const float* pol_b2  = (const float*)d_in[18];
    float* out = (float*)d_out;

    fold_kernel<<<dim3(32, 3), 256>>>(node_W, nbr_W, gud_W, enc_W);
    cb_kernel<<<1, 512>>>(node_b, nbr_b, gud_b, enc_W, enc_b);

    cudaFuncSetAttribute(node_mma_direct,
                         cudaFuncAttributeMaxDynamicSharedMemorySize, NSMEM);
    node_mma_direct<<<NODE_GRID, 512, NSMEM>>>(x, gf);

    cudaFuncSetAttribute(edge_kernel_mma,
                         cudaFuncAttributeMaxDynamicSharedMemorySize, SMEM_E);
    edge_kernel_mma<<<NGRID, 256, SMEM_E>>>(ei, vp_W1, vp_b1, vp_W2, vp_b2,
                                            pol_W1, pol_b1, pol_W2, pol_b2, out);
}

// round 17
// speedup vs baseline: 1.6263x; 1.6263x over previous
#include <cuda_runtime.h>
#include <cuda_bf16.h>
#include <math.h>
#include <stdint.h>

#define NN 50000
#define NE 800000
#define C 128

// Scratch (device globals; no allocation allowed)
// g_M1/2/3 hold the folded matrices TRANSPOSED: g_M[j*C + i] = M[i][j]
__device__ float g_M1[C * C];
__device__ float g_M2[C * C];
__device__ float g_M3[C * C];
__device__ float g_cb[C];
__device__ float g_A[NN * C];
__device__ float g_B[NN * C];

__device__ __forceinline__ uint32_t smem_u32(const void* p) {
    uint32_t a;
    asm("{ .reg .u64 t; cvta.to.shared.u64 t, %1; cvt.u32.u64 %0, t; }"
        : "=r"(a) : "l"(p));
    return a;
}
__device__ __forceinline__ void ldsm_x4(uint32_t* r, uint32_t addr) {
    asm volatile("ldmatrix.sync.aligned.m8n8.x4.shared.b16 {%0,%1,%2,%3}, [%4];"
                 : "=r"(r[0]), "=r"(r[1]), "=r"(r[2]), "=r"(r[3]) : "r"(addr));
}
__device__ __forceinline__ void mma_bf16(float* c, const uint32_t* a,
                                         uint32_t b0, uint32_t b1) {
    asm volatile(
        "mma.sync.aligned.m16n8k16.row.col.f32.bf16.bf16.f32 "
        "{%0,%1,%2,%3}, {%4,%5,%6,%7}, {%8,%9}, {%0,%1,%2,%3};"
        : "+f"(c[0]), "+f"(c[1]), "+f"(c[2]), "+f"(c[3])
        : "r"(a[0]), "r"(a[1]), "r"(a[2]), "r"(a[3]), "r"(b0), "r"(b1));
}
__device__ __forceinline__ void mma3_pair(float* c0, float* c1,
                                          const uint32_t* ah, const uint32_t* al,
                                          const uint32_t* bh, const uint32_t* bl) {
    mma_bf16(c0, ah, bh[0], bh[1]);
    mma_bf16(c0, al, bh[0], bh[1]);
    mma_bf16(c0, ah, bl[0], bl[1]);
    mma_bf16(c1, ah, bh[2], bh[3]);
    mma_bf16(c1, al, bh[2], bh[3]);
    mma_bf16(c1, ah, bl[2], bl[3]);
}
__device__ __forceinline__ void splitf2(float2 v, uint32_t& h, uint32_t& l) {
    __nv_bfloat162 hh = __floats2bfloat162_rn(v.x, v.y);
    __nv_bfloat162 ll = __floats2bfloat162_rn(v.x - __bfloat162float(hh.x),
                                              v.y - __bfloat162float(hh.y));
    h = *(uint32_t*)&hh;
    l = *(uint32_t*)&ll;
}

#define PITCH 272

// ---------------------------------------------------------------------------
// K1: fold the three input linears through enc_W. Stores TRANSPOSED.
// grid (32, 3) = 96 blocks (R15, confirmed win).
// ---------------------------------------------------------------------------
__global__ void fold_kernel(const float* __restrict__ node_W,
                            const float* __restrict__ nbr_W,
                            const float* __restrict__ gud_W,
                            const float* __restrict__ enc_W) {
    int m = blockIdx.y;
    const float* W = (m == 0) ? node_W : ((m == 1) ? nbr_W : gud_W);
    const float* E = enc_W + m * C * C;
    float* M = (m == 0) ? g_M1 : ((m == 1) ? g_M2 : g_M3);

    int j = threadIdx.x & 127;
    int iq = threadIdx.x >> 7;   // 0..1
    int i0 = blockIdx.x * 4;
    for (int i = i0 + iq; i < i0 + 4; i += 2) {
        float s = 0.f;
#pragma unroll 8
        for (int h = 0; h < C; h++) s += W[i * C + h] * E[h * C + j];
        M[j * C + i] = s;   // transposed store
    }
}

// cb: 512 threads, 4-way split over the 384 h-terms, smem reduction (R15).
__global__ void cb_kernel(const float* __restrict__ node_b,
                          const float* __restrict__ nbr_b,
                          const float* __restrict__ gud_b,
                          const float* __restrict__ enc_W,
                          const float* __restrict__ enc_b) {
    __shared__ float part[4][C];
    int j = threadIdx.x & 127;
    int q = threadIdx.x >> 7;   // 0..3
    float s = 0.f;
    for (int h = q * 96; h < (q + 1) * 96; h++) {
        float b = (h < 128) ? node_b[h] : ((h < 256) ? nbr_b[h - 128] : gud_b[h - 256]);
        s += b * enc_W[h * C + j];
    }
    part[q][j] = s;
    __syncthreads();
    if (q == 0)
        g_cb[j] = enc_b[j] + part[0][j] + part[1][j] + part[2][j] + part[3][j];
}

// ---------------------------------------------------------------------------
// K2: single-pass node precompute, 512 threads / 16 warps.
// Symmetric 1-deep register prefetch: BOTH x and g operands for ks+1 are
// issued during ks's MMAs.
// ---------------------------------------------------------------------------
#define NSMEM  208896
#define NODE_GRID 148

__global__ __launch_bounds__(512, 1)
void node_mma_direct(const float* __restrict__ x, const float* __restrict__ g) {
    extern __shared__ float smf[];
    char* smc = (char*)smf;
    uint32_t su = smem_u32(smf);
    int tid = threadIdx.x;
    int tx = tid & 31, wid = tid >> 5;
    int sub = wid & 7, nh = wid >> 3;
    int gwid = blockIdx.x * 8 + sub;

#pragma unroll
    for (int mi = 0; mi < 3; mi++) {
        const float* Wm = (mi == 0) ? g_M1 : ((mi == 1) ? g_M2 : g_M3);
        char* base = smc + mi * 69632;
        for (int idx = tid; idx < C * C; idx += 512) {
            int n = idx >> 7, k = idx & 127;
            float w = Wm[idx];
            __nv_bfloat16 h = __float2bfloat16(w);
            __nv_bfloat16 l = __float2bfloat16(w - __bfloat162float(h));
            *(__nv_bfloat16*)(base + n * PITCH + k * 2) = h;
            *(__nv_bfloat16*)(base + 34816 + n * PITCH + k * 2) = l;
        }
    }
    __syncthreads();

    int gr = tx >> 2;
    int gc2 = (tx & 3) * 2;
    uint32_t b_row = (tx & 7) + 8 * (tx >> 4);
    uint32_t b_k16 = ((tx >> 3) & 1) * 16;
    uint32_t nbase = (uint32_t)(nh * 64);

    const int NTW = NN / 16;
    const int WSTRIDE = NODE_GRID * 8;

    for (int t = gwid; t < NTW; t += WSTRIDE) {
        int row0 = t * 16;
        const float* xr0 = x + (size_t)(row0 + gr) * C + gc2;
        const float* xr8 = xr0 + 8 * C;
        const float* gr0 = g + (size_t)(row0 + gr) * C + gc2;
        const float* gr8 = gr0 + 8 * C;

        float accA[8][4], accB[8][4];
#pragma unroll
        for (int a = 0; a < 8; a++)
#pragma unroll
            for (int b = 0; b < 4; b++) { accA[a][b] = 0.f; accB[a][b] = 0.f; }

        // preload both x and g raw fragments for ks=0
        float2 xv[4], gv[4];
        xv[0] = *(const float2*)(xr0);
        xv[1] = *(const float2*)(xr8);
        xv[2] = *(const float2*)(xr0 + 8);
        xv[3] = *(const float2*)(xr8 + 8);
        gv[0] = *(const float2*)(gr0);
        gv[1] = *(const float2*)(gr8);
        gv[2] = *(const float2*)(gr0 + 8);
        gv[3] = *(const float2*)(gr8 + 8);

#pragma unroll
        for (int ks = 0; ks < 8; ks++) {
            int kb2 = ks * 16 + 16;

            uint32_t ah[4], al[4];
            splitf2(xv[0], ah[0], al[0]);
            splitf2(xv[1], ah[1], al[1]);
            splitf2(xv[2], ah[2], al[2]);
            splitf2(xv[3], ah[3], al[3]);
            uint32_t bcol = ks * 32 + b_k16;

            // prefetch x for ks+1 (hidden under M1/M2 MMAs)
            if (ks < 7) {
                xv[0] = *(const float2*)(xr0 + kb2);
                xv[1] = *(const float2*)(xr8 + kb2);
                xv[2] = *(const float2*)(xr0 + kb2 + 8);
                xv[3] = *(const float2*)(xr8 + kb2 + 8);
            }

#pragma unroll
            for (int np = 0; np < 4; np++) {
                uint32_t bro = (nbase + np * 16 + b_row) * PITCH + bcol;
                uint32_t bh[4], bl[4];
                ldsm_x4(bh, su + bro);
                ldsm_x4(bl, su + 34816 + bro);
                mma3_pair(accA[2 * np], accA[2 * np + 1], ah, al, bh, bl);
                ldsm_x4(bh, su + 69632 + bro);
                ldsm_x4(bl, su + 69632 + 34816 + bro);
                mma3_pair(accB[2 * np], accB[2 * np + 1], ah, al, bh, bl);
            }

            uint32_t gh[4], gl[4];
            splitf2(gv[0], gh[0], gl[0]);
            splitf2(gv[1], gh[1], gl[1]);
            splitf2(gv[2], gh[2], gl[2]);
            splitf2(gv[3], gh[3], gl[3]);

            // prefetch g for ks+1 (hidden under M3 MMAs)
            if (ks < 7) {
                gv[0] = *(const float2*)(gr0 + kb2);
                gv[1] = *(const float2*)(gr8 + kb2);
                gv[2] = *(const float2*)(gr0 + kb2 + 8);
                gv[3] = *(const float2*)(gr8 + kb2 + 8);
            }

#pragma unroll
            for (int np = 0; np < 4; np++) {
                uint32_t bro = (nbase + np * 16 + b_row) * PITCH + bcol;
                uint32_t bh[4], bl[4];
                ldsm_x4(bh, su + 139264 + bro);
                ldsm_x4(bl, su + 139264 + 34816 + bro);
                mma3_pair(accB[2 * np], accB[2 * np + 1], gh, gl, bh, bl);
            }
        }

        float* pa = g_A + (size_t)(row0 + gr) * C + nbase + gc2;
        float* pb = g_B + (size_t)(row0 + gr) * C + nbase + gc2;
#pragma unroll
        for (int nf = 0; nf < 8; nf++) {
            int col = nf * 8;
            *(float2*)(pa + col) = make_float2(accA[nf][0], accA[nf][1]);
            *(float2*)(pa + 8 * C + col) = make_float2(accA[nf][2], accA[nf][3]);
            *(float2*)(pb + col) = make_float2(accB[nf][0], accB[nf][1]);
            *(float2*)(pb + 8 * C + col) = make_float2(accB[nf][2], accB[nf][3]);
        }
    }
}

// ---------------------------------------------------------------------------
// K3: split-bf16 edge kernel (FROZEN R13 structure: 8 warps, warp-private,
// no block barriers; 198 regs; 6x-confirmed optimum).
// SMEM (bytes):
//   [0..1536)        params: vb1[64] vw2[64] pb1[128] pw2[128] (floats)
//   [2048..71680)    A: 8 warps x (hi 16x272B + lo 16x272B) = 8704 B/warp
//   [71680..123904)  B hi: 192 rows x 272 B
//   [123904..176128) B lo
// ---------------------------------------------------------------------------
#define A_OFF    2048
#define A_WARP   (2 * 16 * PITCH)          // 8704
#define B_H_OFF  (A_OFF + 8 * A_WARP)      // 71680
#define B_L_OFF  (B_H_OFF + 192 * PITCH)   // 123904
#define SMEM_E   (B_L_OFF + 192 * PITCH)   // 176128
#define NGRID    148

__global__ __launch_bounds__(256, 1)
void edge_kernel_mma(const int* __restrict__ ei,
                     const float* __restrict__ vp_W1, const float* __restrict__ vp_b1,
                     const float* __restrict__ vp_W2, const float* __restrict__ vp_b2,
                     const float* __restrict__ pol_W1, const float* __restrict__ pol_b1,
                     const float* __restrict__ pol_W2, const float* __restrict__ pol_b2,
                     float* __restrict__ out) {
    extern __shared__ float smf[];
    char* smc = (char*)smf;
    uint32_t su = smem_u32(smf);
    int tid = threadIdx.x;
    int tx = tid & 31, wid = tid >> 5;

    // --- stage split weights B[n][k]; n fastest-varying -> coalesced reads ---
    for (int idx = tid; idx < 192 * C; idx += 256) {
        int k = idx / 192, n = idx % 192;
        float w = (n < 64) ? vp_W1[k * 64 + n] : pol_W1[k * C + (n - 64)];
        __nv_bfloat16 wh = __float2bfloat16(w);
        __nv_bfloat16 wl = __float2bfloat16(w - __bfloat162float(wh));
        *(__nv_bfloat16*)(smc + B_H_OFF + n * PITCH + k * 2) = wh;
        *(__nv_bfloat16*)(smc + B_L_OFF + n * PITCH + k * 2) = wl;
    }
    if (tid < 64) { smf[tid] = vp_b1[tid]; smf[64 + tid] = vp_W2[tid]; }
    if (tid < 128) { smf[128 + tid] = pol_b1[tid]; smf[256 + tid] = pol_W2[tid]; }
    __syncthreads();

    float vb2v = vp_b2[0], pb2v = pol_b2[0];
    float4 cb4 = ((const float4*)g_cb)[tx];
    if (blockIdx.x == 0 && tid == 0) out[3L * NE] = 0.f;  // value_loss

    uint32_t awu = su + A_OFF + wid * A_WARP;
    uint32_t a_row = (tx & 7) + 8 * ((tx >> 3) & 1);
    uint32_t a_k16 = (tx >> 4) * 16;
    uint32_t b_row = (tx & 7) + 8 * (tx >> 4);
    uint32_t b_k16 = ((tx >> 3) & 1) * 16;

    const int ntiles = NE / 128;  // 6250
    for (int t = blockIdx.x; t < ntiles; t += NGRID) {
        long base = (long)t * 128 + wid * 16;

        __syncwarp();
#pragma unroll 4
        for (int m = 0; m < 16; m++) {
            int rr = ei[base + m];
            int cc = ei[NE + base + m];
            float4 a = ((const float4*)(g_A + (size_t)rr * C))[tx];
            float4 b = ((const float4*)(g_B + (size_t)cc * C))[tx];
            float z0 = fmaxf(a.x + b.x + cb4.x, 0.f);
            float z1 = fmaxf(a.y + b.y + cb4.y, 0.f);
            float z2 = fmaxf(a.z + b.z + cb4.z, 0.f);
            float z3 = fmaxf(a.w + b.w + cb4.w, 0.f);
            __nv_bfloat162 h01 = __floats2bfloat162_rn(z0, z1);
            __nv_bfloat162 h23 = __floats2bfloat162_rn(z2, z3);
            __nv_bfloat162 l01 = __floats2bfloat162_rn(
                z0 - __bfloat162float(h01.x), z1 - __bfloat162float(h01.y));
            __nv_bfloat162 l23 = __floats2bfloat162_rn(
                z2 - __bfloat162float(h23.x), z3 - __bfloat162float(h23.y));
            uint2 hv, lv;
            hv.x = *(uint32_t*)&h01; hv.y = *(uint32_t*)&h23;
            lv.x = *(uint32_t*)&l01; lv.y = *(uint32_t*)&l23;
            *(uint2*)(smc + (awu - su) + m * PITCH + tx * 8) = hv;
            *(uint2*)(smc + (awu - su) + 16 * PITCH + m * PITCH + tx * 8) = lv;
        }
        __syncwarp();

        float acc[24][4];
#pragma unroll
        for (int a = 0; a < 24; a++)
#pragma unroll
            for (int b = 0; b < 4; b++) acc[a][b] = 0.f;

        for (int ks = 0; ks < 8; ks++) {
            uint32_t ah[4], al[4];
            uint32_t acol = ks * 32 + a_k16;
            ldsm_x4(ah, awu + a_row * PITCH + acol);
            ldsm_x4(al, awu + 16 * PITCH + a_row * PITCH + acol);
            uint32_t bcol = ks * 32 + b_k16;
#pragma unroll
            for (int np = 0; np < 12; np++) {
                uint32_t bro = (np * 16 + b_row) * PITCH + bcol;
                uint32_t bh[4], bl[4];
                ldsm_x4(bh, su + B_H_OFF + bro);
                ldsm_x4(bl, su + B_L_OFF + bro);
                mma3_pair(acc[2 * np], acc[2 * np + 1], ah, al, bh, bl);
            }
        }

        float vr = 0.f, vr8 = 0.f, lr = 0.f, lr8 = 0.f;
#pragma unroll
        for (int nt = 0; nt < 24; nt++) {
            int c0 = nt * 8 + 2 * (tx & 3);
            if (nt < 8) {
                float b0 = smf[c0], w0 = smf[64 + c0];
                float b1 = smf[c0 + 1], w1 = smf[64 + c0 + 1];
                vr  += fmaxf(acc[nt][0] + b0, 0.f) * w0 + fmaxf(acc[nt][1] + b1, 0.f) * w1;
                vr8 += fmaxf(acc[nt][2] + b0, 0.f) * w0 + fmaxf(acc[nt][3] + b1, 0.f) * w1;
            } else {
                int ix = c0 - 64;
                float b0 = smf[128 + ix], w0 = smf[256 + ix];
                float b1 = smf[128 + ix + 1], w1 = smf[256 + ix + 1];
                lr  += fmaxf(acc[nt][0] + b0, 0.f) * w0 + fmaxf(acc[nt][1] + b1, 0.f) * w1;
                lr8 += fmaxf(acc[nt][2] + b0, 0.f) * w0 + fmaxf(acc[nt][3] + b1, 0.f) * w1;
            }
        }
#pragma unroll
        for (int off = 1; off <= 2; off <<= 1) {
            vr  += __shfl_xor_sync(0xffffffffu, vr, off);
            vr8 += __shfl_xor_sync(0xffffffffu, vr8, off);
            lr  += __shfl_xor_sync(0xffffffffu, lr, off);
            lr8 += __shfl_xor_sync(0xffffffffu, lr8, off);
        }
        if ((tx & 3) == 0) {
            int r = tx >> 2;
            long e0 = base + r;
            long e1 = base + r + 8;
            float v0 = vr + vb2v, v1 = vr8 + vb2v;
            float p0 = 1.f / (1.f + __expf(-(lr + pb2v)));
            float p1 = 1.f / (1.f + __expf(-(lr8 + pb2v)));
            out[e0] = v0;
            out[e1] = v1;
            out[NE + e0] = p0;
            out[NE + e1] = p1;
            out[2L * NE + e0] = (p0 > 0.5f) ? 1.f : 0.f;
            out[2L * NE + e1] = (p1 > 0.5f) ? 1.f : 0.f;
        }
    }
}

// ---------------------------------------------------------------------------
extern "C" void kernel_launch(void* const* d_in, const int* in_sizes, int n_in,
                              void* d_out, int out_size) {
    const float* x       = (const float*)d_in[0];
    const int*   ei      = (const int*)d_in[1];
    const float* gf      = (const float*)d_in[2];
    const float* node_W  = (const float*)d_in[3];
    const float* node_b  = (const float*)d_in[4];
    const float* nbr_W   = (const float*)d_in[5];
    const float* nbr_b   = (const float*)d_in[6];
    const float* gud_W   = (const float*)d_in[7];
    const float* gud_b   = (const float*)d_in[8];
    const float* enc_W   = (const float*)d_in[9];
    const float* enc_b   = (const float*)d_in[10];
    const float* vp_W1   = (const float*)d_in[11];
    const float* vp_b1   = (const float*)d_in[12];
    const float* vp_W2   = (const float*)d_in[13];
    const float* vp_b2   = (const float*)d_in[14];
    const float* pol_W1  = (const float*)d_in[15];
    const float* pol_b1  = (const float*)d_in[16];
    const float* pol_W2  = (const float*)d_in[17];
    const float* pol_b2  = (const float*)d_in[18];
    float* out = (float*)d_out;

    fold_kernel<<<dim3(32, 3), 256>>>(node_W, nbr_W, gud_W, enc_W);
    cb_kernel<<<1, 512>>>(node_b, nbr_b, gud_b, enc_W, enc_b);

    cudaFuncSetAttribute(node_mma_direct,
                         cudaFuncAttributeMaxDynamicSharedMemorySize, NSMEM);
    node_mma_direct<<<NODE_GRID, 512, NSMEM>>>(x, gf);

    cudaFuncSetAttribute(edge_kernel_mma,
                         cudaFuncAttributeMaxDynamicSharedMemorySize, SMEM_E);
    edge_kernel_mma<<<NGRID, 256, SMEM_E>>>(ei, vp_W1, vp_b1, vp_W2, vp_b2,
                                            pol_W1, pol_b1, pol_W2, pol_b2, out);
}